// round 1
// baseline (speedup 1.0000x reference)
#include <cuda_runtime.h>
#include <math.h>

// ---------------- problem constants ----------------
#define BATCH   4
#define SEQ     2048
#define DIM     1024
#define NHEADS  8
#define HDIM    128
#define WINDOW  16
#define EPSV    1e-6f
#define MROWS   (BATCH * SEQ)          // 8192

// ---------------- device scratch (static; no runtime allocs) ----------------
__device__ float g_xq[MROWS * DIM];
__device__ float g_xk[MROWS * DIM];
__device__ float g_xv[MROWS * DIM];
__device__ float g_y [MROWS * DIM];

// ---------------- SGEMM: C[M,N] = A[M,K] @ B[K,N], fp32 ----------------
#define BM 128
#define BN 128
#define BK 8
#define TM 8
#define TN 8

__global__ __launch_bounds__(256, 2)
void sgemm_kernel(const float* __restrict__ A, const float* __restrict__ B,
                  float* __restrict__ C, int M, int N, int K)
{
    __shared__ float As[BK][BM];
    __shared__ float Bs[BK][BN];

    const int tid = threadIdx.x;
    const int bm = blockIdx.y * BM;
    const int bn = blockIdx.x * BN;

    // load indexing
    const int a_row = tid >> 1;            // 0..127
    const int a_col = (tid & 1) * 4;       // 0 or 4
    const int b_row = tid >> 5;            // 0..7
    const int b_col = (tid & 31) * 4;      // 0..124

    const float* Aptr = A + (size_t)(bm + a_row) * K;
    const float* Bptr = B + bn;

    // compute indexing: 16x16 grid of threads, each 8x8 outputs
    const int ty = (tid >> 4) * TM;        // 0..120
    const int tx = (tid & 15) * TN;        // 0..120

    float acc[TM][TN];
#pragma unroll
    for (int i = 0; i < TM; i++)
#pragma unroll
        for (int j = 0; j < TN; j++) acc[i][j] = 0.0f;

    for (int k0 = 0; k0 < K; k0 += BK) {
        float4 av = *(const float4*)(Aptr + k0 + a_col);
        float4 bv = *(const float4*)(Bptr + (size_t)(k0 + b_row) * N + b_col);
        As[a_col + 0][a_row] = av.x;
        As[a_col + 1][a_row] = av.y;
        As[a_col + 2][a_row] = av.z;
        As[a_col + 3][a_row] = av.w;
        *(float4*)&Bs[b_row][b_col] = bv;
        __syncthreads();

#pragma unroll
        for (int kk = 0; kk < BK; kk++) {
            float ar[TM], br[TN];
            float4 a0 = *(const float4*)&As[kk][ty];
            float4 a1 = *(const float4*)&As[kk][ty + 4];
            float4 b0 = *(const float4*)&Bs[kk][tx];
            float4 b1 = *(const float4*)&Bs[kk][tx + 4];
            ar[0]=a0.x; ar[1]=a0.y; ar[2]=a0.z; ar[3]=a0.w;
            ar[4]=a1.x; ar[5]=a1.y; ar[6]=a1.z; ar[7]=a1.w;
            br[0]=b0.x; br[1]=b0.y; br[2]=b0.z; br[3]=b0.w;
            br[4]=b1.x; br[5]=b1.y; br[6]=b1.z; br[7]=b1.w;
#pragma unroll
            for (int i = 0; i < TM; i++)
#pragma unroll
                for (int j = 0; j < TN; j++)
                    acc[i][j] = fmaf(ar[i], br[j], acc[i][j]);
        }
        __syncthreads();
    }

    float* Cptr = C + (size_t)(bm + ty) * N + bn + tx;
#pragma unroll
    for (int i = 0; i < TM; i++) {
        float4 v0 = {acc[i][0], acc[i][1], acc[i][2], acc[i][3]};
        float4 v1 = {acc[i][4], acc[i][5], acc[i][6], acc[i][7]};
        *(float4*)(Cptr + (size_t)i * N)     = v0;
        *(float4*)(Cptr + (size_t)i * N + 4) = v1;
    }
}

// ---------------- RMSNorm (in place, row = 1024 floats) ----------------
__global__ __launch_bounds__(256)
void rmsnorm_kernel(float* __restrict__ x, const float* __restrict__ w)
{
    const int row = blockIdx.x;
    const int tid = threadIdx.x;
    float* xr = x + (size_t)row * DIM;

    // each thread owns one float4 (256*4 = 1024)
    float4 v = *(const float4*)(xr + tid * 4);
    float ss = v.x*v.x + v.y*v.y + v.z*v.z + v.w*v.w;

    __shared__ float red[8];
#pragma unroll
    for (int o = 16; o; o >>= 1) ss += __shfl_xor_sync(0xFFFFFFFFu, ss, o);
    if ((tid & 31) == 0) red[tid >> 5] = ss;
    __syncthreads();
    if (tid < 32) {
        float s = (tid < 8) ? red[tid] : 0.0f;
#pragma unroll
        for (int o = 4; o; o >>= 1) s += __shfl_xor_sync(0xFFFFFFFFu, s, o);
        if (tid == 0) red[0] = s;
    }
    __syncthreads();

    const float rs = rsqrtf(red[0] * (1.0f / DIM) + EPSV);
    float4 wv = *(const float4*)(w + tid * 4);
    v.x *= rs * wv.x; v.y *= rs * wv.y; v.z *= rs * wv.z; v.w *= rs * wv.w;
    *(float4*)(xr + tid * 4) = v;
}

// ---------------- banded attention: one warp per (b, t, h) ----------------
__global__ __launch_bounds__(256)
void attn_kernel(const float* __restrict__ xq, const float* __restrict__ xk,
                 const float* __restrict__ xv, float* __restrict__ y)
{
    const int gw   = (blockIdx.x * blockDim.x + threadIdx.x) >> 5;
    const int lane = threadIdx.x & 31;
    // gw decodes as (b, t, h); total B*T*H warps
    const int h = gw & (NHEADS - 1);
    const int t = (gw >> 3) & (SEQ - 1);
    const int b = gw >> 14;                       // SEQ*NHEADS = 16384

    const size_t rowq = ((size_t)(b * SEQ + t)) * DIM + h * HDIM;
    const float4 q = *(const float4*)(xq + rowq + lane * 4);

    const float scale = 0.08838834764831845f;     // 1/sqrt(128)
    const float slope = exp2f(-(float)h);         // ALiBi slopes for H=8

    float scores[WINDOW + 1];
    float mx = -1e30f;

#pragma unroll
    for (int jj = 0; jj <= WINDOW; jj++) {
        const int j = t - WINDOW + jj;
        float s = -1e30f;
        if (j >= 0) {
            const size_t rowk = ((size_t)(b * SEQ + j)) * DIM + h * HDIM;
            const float4 k = *(const float4*)(xk + rowk + lane * 4);
            float d = q.x*k.x + q.y*k.y + q.z*k.z + q.w*k.w;
#pragma unroll
            for (int o = 16; o; o >>= 1) d += __shfl_xor_sync(0xFFFFFFFFu, d, o);
            s = d * scale + slope * (float)(j - t);
        }
        scores[jj] = s;
        mx = fmaxf(mx, s);
    }

    float l = 0.0f;
#pragma unroll
    for (int jj = 0; jj <= WINDOW; jj++) {
        float e = __expf(scores[jj] - mx);
        scores[jj] = e;
        l += e;
    }
    const float inv = 1.0f / l;

    float4 acc = {0.f, 0.f, 0.f, 0.f};
#pragma unroll
    for (int jj = 0; jj <= WINDOW; jj++) {
        const int j = t - WINDOW + jj;
        if (j >= 0) {
            const size_t rowv = ((size_t)(b * SEQ + j)) * DIM + h * HDIM;
            const float4 v = *(const float4*)(xv + rowv + lane * 4);
            const float p = scores[jj] * inv;
            acc.x = fmaf(p, v.x, acc.x);
            acc.y = fmaf(p, v.y, acc.y);
            acc.z = fmaf(p, v.z, acc.z);
            acc.w = fmaf(p, v.w, acc.w);
        }
    }
    *(float4*)(y + rowq + lane * 4) = acc;
}

// ---------------- launch ----------------
extern "C" void kernel_launch(void* const* d_in, const int* in_sizes, int n_in,
                              void* d_out, int out_size)
{
    const float* x       = (const float*)d_in[0];
    const float* wq      = (const float*)d_in[1];
    const float* wk      = (const float*)d_in[2];
    const float* wv      = (const float*)d_in[3];
    const float* wo      = (const float*)d_in[4];
    const float* qnw     = (const float*)d_in[5];
    const float* knw     = (const float*)d_in[6];
    float* out           = (float*)d_out;

    float *xq, *xk, *xv, *y;
    cudaGetSymbolAddress((void**)&xq, g_xq);
    cudaGetSymbolAddress((void**)&xk, g_xk);
    cudaGetSymbolAddress((void**)&xv, g_xv);
    cudaGetSymbolAddress((void**)&y,  g_y);

    dim3 ggrid(DIM / BN, MROWS / BM);   // (8, 64)
    dim3 gblk(256);

    // QKV projections
    sgemm_kernel<<<ggrid, gblk>>>(x, wq, xq, MROWS, DIM, DIM);
    sgemm_kernel<<<ggrid, gblk>>>(x, wk, xk, MROWS, DIM, DIM);
    sgemm_kernel<<<ggrid, gblk>>>(x, wv, xv, MROWS, DIM, DIM);

    // RMSNorm on q and k (full 1024-dim rows)
    rmsnorm_kernel<<<MROWS, 256>>>(xq, qnw);
    rmsnorm_kernel<<<MROWS, 256>>>(xk, knw);

    // banded attention: B*T*H warps, 8 warps per block
    const int total_warps = BATCH * SEQ * NHEADS;     // 65536
    attn_kernel<<<total_warps / 8, 256>>>(xq, xk, xv, y);

    // output projection
    sgemm_kernel<<<ggrid, gblk>>>(y, wo, out, MROWS, DIM, DIM);
}